// round 4
// baseline (speedup 1.0000x reference)
#include <cuda_runtime.h>
#include <math.h>
#include <stdint.h>

#define BB 64      // batch
#define TT 512     // seq len
#define DD 512     // input size
#define HH 1024    // hidden
#define G4 4096    // 4*HH
#define NBLK 128   // persistent blocks for recurrent phase

// ---------------- scratch (static __device__, no allocs) ----------------
__device__ float g_G[(size_t)TT * BB * G4];      // precomputed x@W+b, rows = (t,B)
__device__ float g_hseq[(size_t)TT * BB * HH];   // layer-0 hidden sequence (T,B,H)
__device__ float g_Up0[(size_t)HH * G4];         // U0 permuted to (k, u, gate)
__device__ float g_Up1[(size_t)HH * G4];         // U1 permuted
__device__ float g_hping[2 * BB * HH];           // h ping-pong
__device__ float g_c[BB * HH];                   // cell state

// ---------------- software grid barrier (graph-replay safe: monotonic gen) --
__device__ unsigned g_cnt = 0;
__device__ volatile unsigned g_gen = 0;

__device__ __forceinline__ void grid_barrier() {
    __syncthreads();
    if (threadIdx.x == 0) {
        __threadfence();
        unsigned old = g_gen;
        if (atomicAdd(&g_cnt, 1) == NBLK - 1) {
            g_cnt = 0;
            __threadfence();
            g_gen = old + 1;
        } else {
            while (g_gen == old) { }
        }
        __threadfence();
    }
    __syncthreads();
}

__device__ __forceinline__ float d_sigmoid(float x) { return 1.0f / (1.0f + expf(-x)); }
__device__ __forceinline__ float d_tanh(float x)    { return 1.0f - 2.0f / (expf(2.0f * x) + 1.0f); }

// ---------------- tf32 helpers ----------------
__device__ __forceinline__ uint32_t f2tf(float x) {
    uint32_t r; asm("cvt.rna.tf32.f32 %0, %1;" : "=r"(r) : "f"(x)); return r;
}
__device__ __forceinline__ void cvt_pair(float x, uint32_t& hi, uint32_t& lo) {
    hi = f2tf(x);
    lo = f2tf(x - __uint_as_float(hi));
}
__device__ __forceinline__ void mma8(float* c, const uint32_t* a, const uint32_t* b) {
    asm volatile("mma.sync.aligned.m16n8k8.row.col.f32.tf32.tf32.f32 "
        "{%0,%1,%2,%3}, {%4,%5,%6,%7}, {%8,%9}, {%0,%1,%2,%3};\n"
        : "+f"(c[0]), "+f"(c[1]), "+f"(c[2]), "+f"(c[3])
        : "r"(a[0]), "r"(a[1]), "r"(a[2]), "r"(a[3]), "r"(b[0]), "r"(b[1]));
}

// ---------------- U permute: Up[(k*HH + u)*4 + g] = U[k*4H + g*H + u] -------
__global__ void permuteU(const float* __restrict__ U, float* __restrict__ Up) {
    int idx = blockIdx.x * blockDim.x + threadIdx.x;   // over HH*HH
    if (idx >= HH * HH) return;
    int k = idx >> 10;
    int u = idx & (HH - 1);
    const float* src = U + (size_t)k * G4 + u;
    float4 v = make_float4(src[0], src[HH], src[2 * HH], src[3 * HH]);
    ((float4*)Up)[idx] = v;
}

// ---------------- tensor-core 3xTF32 GEMM ----------------
// C[m][n] = A[rowmap(m)][:] @ W[:, n] + bias[n],  C is (32768, 4096)
// mode 0: rowmap(m) = (m % 64)*TT + (m / 64)   (X is (B,T,D); G rows are (t,b))
// mode 1: rowmap(m) = m                        (hseq stored (T,B,H))
// Block tile 128(M) x 64(N), KT=16. 8 warps: warp (wm 0..3, wn 0..1), 32x32 warp tile.
#define KT 16
#define AS_STR 132
#define BS_STR 20
#define ASZ (KT * AS_STR)         // 2112 words
#define BSZ (64 * BS_STR)         // 1280 words
#define BUFSZ (2 * ASZ + 2 * BSZ) // 6784 words per buffer
#define GSMEM (2 * BUFSZ * 4)     // 54272 bytes

__global__ __launch_bounds__(256, 2) void gemm_tf32(
    const float* __restrict__ A, const float* __restrict__ W,
    const float* __restrict__ bias, float* __restrict__ C, int K, int mode)
{
    extern __shared__ uint32_t sm[];
    int tid = threadIdx.x;
    int lane = tid & 31, wid = tid >> 5;
    int wm = wid & 3, wn = wid >> 1 >> 1;   // wn = wid>>2
    wn = wid >> 2;
    int m0 = blockIdx.y * 128, n0 = blockIdx.x * 64;

    // A staging assignment: thread loads rows amA and amA+64, 4 consecutive k
    int amA = tid >> 2;          // 0..63
    int akA = (tid & 3) * 4;     // 0,4,8,12
    int mA0 = m0 + amA, mA1 = mA0 + 64;
    size_t r0 = (mode == 0) ? (size_t)(mA0 & 63) * TT + (mA0 >> 6) : (size_t)mA0;
    size_t r1 = (mode == 0) ? (size_t)(mA1 & 63) * TT + (mA1 >> 6) : (size_t)mA1;
    const float* pA0 = A + r0 * K + akA;
    const float* pA1 = A + r1 * K + akA;
    // B staging: thread loads W[kc+bkB][n0+bnB .. +3]
    int bkB = tid >> 4;          // 0..15
    int bnB = (tid & 15) * 4;    // 0..60
    const float* pB = W + (size_t)bkB * G4 + n0 + bnB;

    float4 fa0 = *(const float4*)pA0; pA0 += KT;
    float4 fa1 = *(const float4*)pA1; pA1 += KT;
    float4 fb  = *(const float4*)pB;  pB  += (size_t)KT * G4;

    float acc[2][4][4];
#pragma unroll
    for (int mt = 0; mt < 2; mt++)
#pragma unroll
        for (int nt = 0; nt < 4; nt++)
#pragma unroll
            for (int i = 0; i < 4; i++) acc[mt][nt][i] = 0.0f;

    int nIter = K / KT;
    for (int it = 0; it < nIter; it++) {
        uint32_t* base = sm + (it & 1) * BUFSZ;
        uint32_t* ah = base;
        uint32_t* al = base + ASZ;
        uint32_t* bh = base + 2 * ASZ;
        uint32_t* bl = bh + BSZ;

        // stage current regs -> smem (convert to hi/lo tf32)
        {
            float va[4]  = {fa0.x, fa0.y, fa0.z, fa0.w};
            float va2[4] = {fa1.x, fa1.y, fa1.z, fa1.w};
            float vw[4]  = {fb.x, fb.y, fb.z, fb.w};
#pragma unroll
            for (int j = 0; j < 4; j++) {
                uint32_t h, l;
                cvt_pair(va[j], h, l);
                ah[(akA + j) * AS_STR + amA] = h;
                al[(akA + j) * AS_STR + amA] = l;
                cvt_pair(va2[j], h, l);
                ah[(akA + j) * AS_STR + amA + 64] = h;
                al[(akA + j) * AS_STR + amA + 64] = l;
                cvt_pair(vw[j], h, l);
                bh[(bnB + j) * BS_STR + bkB] = h;
                bl[(bnB + j) * BS_STR + bkB] = l;
            }
        }
        __syncthreads();

        // prefetch next gmem tile (lands during compute)
        if (it + 1 < nIter) {
            fa0 = *(const float4*)pA0; pA0 += KT;
            fa1 = *(const float4*)pA1; pA1 += KT;
            fb  = *(const float4*)pB;  pB  += (size_t)KT * G4;
        }

        // compute: 2 k8 sub-steps
#pragma unroll
        for (int ks = 0; ks < 2; ks++) {
            int kb = ks * 8 + (lane & 3);
            int ar = wm * 32 + (lane >> 2);
            uint32_t Ah[2][4], Al[2][4];
#pragma unroll
            for (int mt = 0; mt < 2; mt++) {
                int r = ar + mt * 16;
                Ah[mt][0] = ah[kb * AS_STR + r];
                Ah[mt][1] = ah[kb * AS_STR + r + 8];
                Ah[mt][2] = ah[(kb + 4) * AS_STR + r];
                Ah[mt][3] = ah[(kb + 4) * AS_STR + r + 8];
                Al[mt][0] = al[kb * AS_STR + r];
                Al[mt][1] = al[kb * AS_STR + r + 8];
                Al[mt][2] = al[(kb + 4) * AS_STR + r];
                Al[mt][3] = al[(kb + 4) * AS_STR + r + 8];
            }
            int bn = wn * 32 + (lane >> 2);
            int bk = ks * 8 + (lane & 3);
            uint32_t Bh[4][2], Bl[4][2];
#pragma unroll
            for (int nt = 0; nt < 4; nt++) {
                Bh[nt][0] = bh[(bn + nt * 8) * BS_STR + bk];
                Bh[nt][1] = bh[(bn + nt * 8) * BS_STR + bk + 4];
                Bl[nt][0] = bl[(bn + nt * 8) * BS_STR + bk];
                Bl[nt][1] = bl[(bn + nt * 8) * BS_STR + bk + 4];
            }
#pragma unroll
            for (int mt = 0; mt < 2; mt++)
#pragma unroll
                for (int nt = 0; nt < 4; nt++) {
                    mma8(acc[mt][nt], Ah[mt], Bh[nt]);   // hi*hi
                    mma8(acc[mt][nt], Al[mt], Bh[nt]);   // lo*hi
                    mma8(acc[mt][nt], Ah[mt], Bl[nt]);   // hi*lo
                }
        }
        // no trailing sync needed: next iteration stages the OTHER buffer,
        // and its __syncthreads orders reuse two iterations apart.
    }

    // epilogue: add bias, store fp32
#pragma unroll
    for (int mt = 0; mt < 2; mt++)
#pragma unroll
        for (int nt = 0; nt < 4; nt++) {
            int gr = m0 + wm * 32 + mt * 16 + (lane >> 2);
            int gc = n0 + wn * 32 + nt * 8 + (lane & 3) * 2;
            float bz0 = bias[gc], bz1 = bias[gc + 1];
            float2 v0 = make_float2(acc[mt][nt][0] + bz0, acc[mt][nt][1] + bz1);
            float2 v1 = make_float2(acc[mt][nt][2] + bz0, acc[mt][nt][3] + bz1);
            *(float2*)&C[(size_t)gr * G4 + gc] = v0;
            *(float2*)&C[(size_t)(gr + 8) * G4 + gc] = v1;
        }
}

// ---------------- persistent recurrent layer (unchanged from R3) ----------
#define HS_STRIDE 66

__global__ __launch_bounds__(256) void lstm_layer(
    const float* __restrict__ Gbase,  // (T, B, 4H) pre-activations
    const float* __restrict__ Up,     // permuted U: (H, H, 4)
    const float* __restrict__ h0,
    const float* __restrict__ c0,
    float* __restrict__ hbuf,         // 2*(B,H) ping-pong
    float* __restrict__ cbuf,         // (B,H)
    float* __restrict__ seq_out,      // h_t at seq_out[t*t_str + b*b_str + u]
    int t_str, int b_str,
    float* hT, float* cT)
{
    __shared__ float hs[128 * HS_STRIDE];
    int tid = threadIdx.x;
    int ju = tid & 7;
    int bg = tid >> 3;
    int b0 = bg * 2;
    int u  = blockIdx.x * 8 + ju;

    for (int i = blockIdx.x * 256 + tid; i < BB * HH; i += NBLK * 256) {
        hbuf[i] = h0[i];
        cbuf[i] = c0[i];
    }

    const float4* UpV = (const float4*)Up + u;

    for (int t = 0; t < TT; t++) {
        grid_barrier();

        const float* Grow = Gbase + (size_t)t * BB * G4;
        const float* h_in = hbuf + (size_t)(t & 1) * BB * HH;
        float* h_out      = hbuf + (size_t)((t + 1) & 1) * BB * HH;

        float a00, a01, a02, a03, a10, a11, a12, a13;
        a00 = Grow[(size_t)b0 * G4 + 0 * HH + u];
        a01 = Grow[(size_t)b0 * G4 + 1 * HH + u];
        a02 = Grow[(size_t)b0 * G4 + 2 * HH + u];
        a03 = Grow[(size_t)b0 * G4 + 3 * HH + u];
        a10 = Grow[(size_t)(b0 + 1) * G4 + 0 * HH + u];
        a11 = Grow[(size_t)(b0 + 1) * G4 + 1 * HH + u];
        a12 = Grow[(size_t)(b0 + 1) * G4 + 2 * HH + u];
        a13 = Grow[(size_t)(b0 + 1) * G4 + 3 * HH + u];

        for (int kc = 0; kc < HH; kc += 128) {
#pragma unroll
            for (int i = 0; i < 8; i++) {
                int lid = tid + i * 256;
                int b = lid >> 5;
                int k = lid & 31;
#pragma unroll
                for (int j = 0; j < 4; j++)
                    hs[(k + 32 * j) * HS_STRIDE + b] = h_in[(size_t)b * HH + kc + k + 32 * j];
            }
            __syncthreads();
#pragma unroll 8
            for (int kk = 0; kk < 128; kk++) {
                float2 h01 = *(const float2*)&hs[kk * HS_STRIDE + b0];
                float4 u4 = UpV[(size_t)(kc + kk) * HH];
                a00 += h01.x * u4.x;  a10 += h01.y * u4.x;
                a01 += h01.x * u4.y;  a11 += h01.y * u4.y;
                a02 += h01.x * u4.z;  a12 += h01.y * u4.z;
                a03 += h01.x * u4.w;  a13 += h01.y * u4.w;
            }
            __syncthreads();
        }

        bool last = (t == TT - 1);
#pragma unroll
        for (int p = 0; p < 2; p++) {
            float gi = p ? a10 : a00;
            float gf = p ? a11 : a01;
            float gg = p ? a12 : a02;
            float go = p ? a13 : a03;
            int b = b0 + p;
            int ci = b * HH + u;
            float ig = d_sigmoid(gi);
            float fg = d_sigmoid(gf);
            float gv = d_tanh(gg);
            float og = d_sigmoid(go);
            float cn = fg * cbuf[ci] + ig * gv;
            float hn = og * d_tanh(cn);
            cbuf[ci] = cn;
            h_out[ci] = hn;
            seq_out[(size_t)t * t_str + (size_t)b * b_str + u] = hn;
            if (last && hT) { hT[ci] = hn; cT[ci] = cn; }
        }
    }
}

// ---------------- launch ----------------
extern "C" void kernel_launch(void* const* d_in, const int* in_sizes, int n_in,
                              void* d_out, int out_size)
{
    const float* X  = (const float*)d_in[0];
    const float* h0 = (const float*)d_in[1];
    const float* c0 = (const float*)d_in[2];
    const float* W0 = (const float*)d_in[3];
    const float* U0 = (const float*)d_in[4];
    const float* b0 = (const float*)d_in[5];
    const float* W1 = (const float*)d_in[6];
    const float* U1 = (const float*)d_in[7];
    const float* b1 = (const float*)d_in[8];
    float* out = (float*)d_out;

    float *G, *hseq, *Up0, *Up1, *hping, *cb;
    cudaGetSymbolAddress((void**)&G,     g_G);
    cudaGetSymbolAddress((void**)&hseq,  g_hseq);
    cudaGetSymbolAddress((void**)&Up0,   g_Up0);
    cudaGetSymbolAddress((void**)&Up1,   g_Up1);
    cudaGetSymbolAddress((void**)&hping, g_hping);
    cudaGetSymbolAddress((void**)&cb,    g_c);

    cudaFuncSetAttribute(gemm_tf32, cudaFuncAttributeMaxDynamicSharedMemorySize, GSMEM);

    permuteU<<<(HH * HH) / 256, 256>>>(U0, Up0);
    permuteU<<<(HH * HH) / 256, 256>>>(U1, Up1);

    dim3 ggrid(G4 / 64, (TT * BB) / 128);   // (64, 256)

    bool wantHC = (size_t)out_size >= (size_t)BB * TT * HH + 2ull * BB * HH;
    float* hT = wantHC ? out + (size_t)BB * TT * HH : nullptr;
    float* cT = wantHC ? hT + (size_t)BB * HH : nullptr;

    // ---- layer 0 ----
    gemm_tf32<<<ggrid, 256, GSMEM>>>(X, W0, b0, G, DD, 0);
    lstm_layer<<<NBLK, 256>>>(G, Up0, h0, c0, hping, cb,
                              hseq, BB * HH, HH,
                              nullptr, nullptr);

    // ---- layer 1 ----
    gemm_tf32<<<ggrid, 256, GSMEM>>>(hseq, W1, b1, G, HH, 1);
    lstm_layer<<<NBLK, 256>>>(G, Up1, h0 + (size_t)BB * HH, c0 + (size_t)BB * HH,
                              hping, cb,
                              out, HH, TT * HH,
                              hT, cT);
}

// round 5
// speedup vs baseline: 2.0286x; 2.0286x over previous
#include <cuda_runtime.h>
#include <math.h>
#include <stdint.h>

#define BB 64      // batch
#define TT 512     // seq len
#define DD 512     // input size
#define HH 1024    // hidden
#define G4 4096    // 4*HH
#define NBLK 128   // persistent blocks (1/SM, co-resident)

// ---------------- scratch (static __device__, no allocs) ----------------
__device__ float g_G[(size_t)TT * BB * G4];      // precomputed x@W+b, rows = (t,B)
__device__ float g_hseq[(size_t)TT * BB * HH];   // layer-0 hidden sequence (T,B,H)
__device__ float2 g_Up0[(size_t)NBLK * HH * 16]; // U0 packed: [blk][k][ju][g] float2 (16MB)
__device__ float2 g_Up1[(size_t)NBLK * HH * 16]; // U1 packed
__device__ float g_hping[2 * BB * HH];           // h ping-pong
__device__ float g_c[BB * HH];                   // (unused placeholder, c in regs now)

// ---------------- software grid barrier (graph-replay safe: monotonic gen) --
__device__ unsigned g_cnt = 0;
__device__ volatile unsigned g_gen = 0;

__device__ __forceinline__ void grid_barrier() {
    __syncthreads();
    if (threadIdx.x == 0) {
        __threadfence();
        unsigned old = g_gen;
        if (atomicAdd(&g_cnt, 1) == NBLK - 1) {
            g_cnt = 0;
            __threadfence();
            g_gen = old + 1;
        } else {
            while (g_gen == old) { }
        }
        __threadfence();
    }
    __syncthreads();
}

__device__ __forceinline__ float d_sigmoid(float x) { return 1.0f / (1.0f + expf(-x)); }
__device__ __forceinline__ float d_tanh(float x)    { return 1.0f - 2.0f / (expf(2.0f * x) + 1.0f); }

// ---------------- tf32 helpers (for the big GEMMs) ----------------
__device__ __forceinline__ uint32_t f2tf(float x) {
    uint32_t r; asm("cvt.rna.tf32.f32 %0, %1;" : "=r"(r) : "f"(x)); return r;
}
__device__ __forceinline__ void cvt_pair(float x, uint32_t& hi, uint32_t& lo) {
    hi = f2tf(x);
    lo = f2tf(x - __uint_as_float(hi));
}
__device__ __forceinline__ void mma8(float* c, const uint32_t* a, const uint32_t* b) {
    asm volatile("mma.sync.aligned.m16n8k8.row.col.f32.tf32.tf32.f32 "
        "{%0,%1,%2,%3}, {%4,%5,%6,%7}, {%8,%9}, {%0,%1,%2,%3};\n"
        : "+f"(c[0]), "+f"(c[1]), "+f"(c[2]), "+f"(c[3])
        : "r"(a[0]), "r"(a[1]), "r"(a[2]), "r"(a[3]), "r"(b[0]), "r"(b[1]));
}

// ---------------- f32x2 packed-FMA helpers ----------------
__device__ __forceinline__ void fma2(uint64_t& acc, uint64_t a, uint64_t b) {
    asm("fma.rn.f32x2 %0, %1, %2, %0;" : "+l"(acc) : "l"(a), "l"(b));
}
__device__ __forceinline__ uint64_t pack_dup(float x) {
    uint64_t r; uint32_t u = __float_as_uint(x);
    asm("mov.b64 %0, {%1, %1};" : "=l"(r) : "r"(u));
    return r;
}
__device__ __forceinline__ uint64_t pack2f(float lo, float hi) {
    uint64_t r;
    asm("mov.b64 %0, {%1, %2};" : "=l"(r) : "r"(__float_as_uint(lo)), "r"(__float_as_uint(hi)));
    return r;
}
__device__ __forceinline__ void unpack2(uint64_t v, float& lo, float& hi) {
    uint32_t a, b;
    asm("mov.b64 {%0, %1}, %2;" : "=r"(a), "=r"(b) : "l"(v));
    lo = __uint_as_float(a); hi = __uint_as_float(b);
}

// ---------------- U pack: Upg[blk][k][ju][g] = (U[k][g*H + u], U[k][g*H + u+1]),
//                  u = blk*8 + 2*ju ----------------
__global__ void packU(const float* __restrict__ U, float2* __restrict__ Upg) {
    int e = blockIdx.x * blockDim.x + threadIdx.x;       // over NBLK*HH*16
    if (e >= NBLK * HH * 16) return;
    int g  = e & 3;
    int ju = (e >> 2) & 3;
    int k  = (e >> 4) & (HH - 1);
    int blk = e >> 14;
    int u = blk * 8 + 2 * ju;
    const float* src = U + (size_t)k * G4 + g * HH + u;
    Upg[e] = make_float2(src[0], src[1]);
}

// ---------------- tensor-core 3xTF32 GEMM (validated R4) ----------------
#define KT 16
#define AS_STR 132
#define BS_STR 20
#define ASZ (KT * AS_STR)
#define BSZ (64 * BS_STR)
#define BUFSZ (2 * ASZ + 2 * BSZ)
#define GSMEM (2 * BUFSZ * 4)

__global__ __launch_bounds__(256, 2) void gemm_tf32(
    const float* __restrict__ A, const float* __restrict__ W,
    const float* __restrict__ bias, float* __restrict__ C, int K, int mode)
{
    extern __shared__ uint32_t sm[];
    int tid = threadIdx.x;
    int lane = tid & 31, wid = tid >> 5;
    int wm = wid & 3, wn = wid >> 2;
    int m0 = blockIdx.y * 128, n0 = blockIdx.x * 64;

    int amA = tid >> 2;
    int akA = (tid & 3) * 4;
    int mA0 = m0 + amA, mA1 = mA0 + 64;
    size_t r0 = (mode == 0) ? (size_t)(mA0 & 63) * TT + (mA0 >> 6) : (size_t)mA0;
    size_t r1 = (mode == 0) ? (size_t)(mA1 & 63) * TT + (mA1 >> 6) : (size_t)mA1;
    const float* pA0 = A + r0 * K + akA;
    const float* pA1 = A + r1 * K + akA;
    int bkB = tid >> 4;
    int bnB = (tid & 15) * 4;
    const float* pB = W + (size_t)bkB * G4 + n0 + bnB;

    float4 fa0 = *(const float4*)pA0; pA0 += KT;
    float4 fa1 = *(const float4*)pA1; pA1 += KT;
    float4 fb  = *(const float4*)pB;  pB  += (size_t)KT * G4;

    float acc[2][4][4];
#pragma unroll
    for (int mt = 0; mt < 2; mt++)
#pragma unroll
        for (int nt = 0; nt < 4; nt++)
#pragma unroll
            for (int i = 0; i < 4; i++) acc[mt][nt][i] = 0.0f;

    int nIter = K / KT;
    for (int it = 0; it < nIter; it++) {
        uint32_t* base = sm + (it & 1) * BUFSZ;
        uint32_t* ah = base;
        uint32_t* al = base + ASZ;
        uint32_t* bh = base + 2 * ASZ;
        uint32_t* bl = bh + BSZ;
        {
            float va[4]  = {fa0.x, fa0.y, fa0.z, fa0.w};
            float va2[4] = {fa1.x, fa1.y, fa1.z, fa1.w};
            float vw[4]  = {fb.x, fb.y, fb.z, fb.w};
#pragma unroll
            for (int j = 0; j < 4; j++) {
                uint32_t h, l;
                cvt_pair(va[j], h, l);
                ah[(akA + j) * AS_STR + amA] = h;
                al[(akA + j) * AS_STR + amA] = l;
                cvt_pair(va2[j], h, l);
                ah[(akA + j) * AS_STR + amA + 64] = h;
                al[(akA + j) * AS_STR + amA + 64] = l;
                cvt_pair(vw[j], h, l);
                bh[(bnB + j) * BS_STR + bkB] = h;
                bl[(bnB + j) * BS_STR + bkB] = l;
            }
        }
        __syncthreads();
        if (it + 1 < nIter) {
            fa0 = *(const float4*)pA0; pA0 += KT;
            fa1 = *(const float4*)pA1; pA1 += KT;
            fb  = *(const float4*)pB;  pB  += (size_t)KT * G4;
        }
#pragma unroll
        for (int ks = 0; ks < 2; ks++) {
            int kb = ks * 8 + (lane & 3);
            int ar = wm * 32 + (lane >> 2);
            uint32_t Ah[2][4], Al[2][4];
#pragma unroll
            for (int mt = 0; mt < 2; mt++) {
                int r = ar + mt * 16;
                Ah[mt][0] = ah[kb * AS_STR + r];
                Ah[mt][1] = ah[kb * AS_STR + r + 8];
                Ah[mt][2] = ah[(kb + 4) * AS_STR + r];
                Ah[mt][3] = ah[(kb + 4) * AS_STR + r + 8];
                Al[mt][0] = al[kb * AS_STR + r];
                Al[mt][1] = al[kb * AS_STR + r + 8];
                Al[mt][2] = al[(kb + 4) * AS_STR + r];
                Al[mt][3] = al[(kb + 4) * AS_STR + r + 8];
            }
            int bn = wn * 32 + (lane >> 2);
            int bk = ks * 8 + (lane & 3);
            uint32_t Bh[4][2], Bl[4][2];
#pragma unroll
            for (int nt = 0; nt < 4; nt++) {
                Bh[nt][0] = bh[(bn + nt * 8) * BS_STR + bk];
                Bh[nt][1] = bh[(bn + nt * 8) * BS_STR + bk + 4];
                Bl[nt][0] = bl[(bn + nt * 8) * BS_STR + bk];
                Bl[nt][1] = bl[(bn + nt * 8) * BS_STR + bk + 4];
            }
#pragma unroll
            for (int mt = 0; mt < 2; mt++)
#pragma unroll
                for (int nt = 0; nt < 4; nt++) {
                    mma8(acc[mt][nt], Ah[mt], Bh[nt]);
                    mma8(acc[mt][nt], Al[mt], Bh[nt]);
                    mma8(acc[mt][nt], Ah[mt], Bl[nt]);
                }
        }
    }
#pragma unroll
    for (int mt = 0; mt < 2; mt++)
#pragma unroll
        for (int nt = 0; nt < 4; nt++) {
            int gr = m0 + wm * 32 + mt * 16 + (lane >> 2);
            int gc = n0 + wn * 32 + nt * 8 + (lane & 3) * 2;
            float bz0 = bias[gc], bz1 = bias[gc + 1];
            float2 v0 = make_float2(acc[mt][nt][0] + bz0, acc[mt][nt][1] + bz1);
            float2 v1 = make_float2(acc[mt][nt][2] + bz0, acc[mt][nt][3] + bz1);
            *(float2*)&C[(size_t)gr * G4 + gc] = v0;
            *(float2*)&C[(size_t)(gr + 8) * G4 + gc] = v1;
        }
}

// ---------------- persistent recurrent layer, smem-U + FFMA2 ----------------
// 128 blocks x 256 threads. Block owns units [blk*8, blk*8+8).
// Thread: ju = tid&3 -> unit pair (2ju, 2ju+1); bg = tid>>2 -> one batch.
// smem: Us (128KB, resident all steps) + hs chunk (33KB).
#define HS_STR 132                      // floats per hs row (64 rows x 132)
#define US_F2 (HH * 16)                 // float2 count of U slice
#define SMEM_LSTM (US_F2 * 8 + BB * HS_STR * 4)   // 131072 + 33792 = 164864 B

__global__ __launch_bounds__(256, 1) void lstm_layer(
    const float* __restrict__ Gbase,   // (T, B, 4H) pre-activations
    const float2* __restrict__ Upg,    // packed U: [blk][k][ju][g] float2
    const float* __restrict__ h0,
    const float* __restrict__ c0,
    float* __restrict__ hbuf,          // 2*(B,H) ping-pong
    float* __restrict__ seq_out,       // h_t at seq_out[t*t_str + b*b_str + u]
    int t_str, int b_str,
    float* hT, float* cT)
{
    extern __shared__ float smf[];
    uint64_t* Us = (uint64_t*)smf;             // [k][ju][g] float2-as-u64
    float* hs = smf + US_F2 * 2;               // [b][k-chunk], stride HS_STR

    int tid = threadIdx.x;
    int ju = tid & 3;
    int bg = tid >> 2;                         // 0..63
    int u0 = blockIdx.x * 8 + 2 * ju;          // even unit of the pair

    // preload U slice into smem (once per layer): 8192 float4
    {
        const float4* src = (const float4*)(Upg + (size_t)blockIdx.x * US_F2);
        float4* dst = (float4*)Us;
#pragma unroll
        for (int i = 0; i < 32; i++)
            dst[tid + i * 256] = src[tid + i * 256];
    }

    // init h ping[0] from h0 (grid-strided); c in registers
    for (int i = blockIdx.x * 256 + tid; i < BB * HH; i += NBLK * 256)
        hbuf[i] = h0[i];
    uint64_t cpair = pack2f(c0[bg * HH + u0], c0[bg * HH + u0 + 1]);

    for (int t = 0; t < TT; t++) {
        grid_barrier();   // h writes from step t-1 (or init) visible everywhere

        const float* Grow = Gbase + (size_t)t * BB * G4 + (size_t)bg * G4;
        const float* h_in = hbuf + (size_t)(t & 1) * BB * HH;
        float* h_out      = hbuf + (size_t)((t + 1) & 1) * BB * HH;

        // init gate accumulators (packed over the unit pair)
        uint64_t acc[4];
#pragma unroll
        for (int g = 0; g < 4; g++)
            acc[g] = pack2f(Grow[g * HH + u0], Grow[g * HH + u0 + 1]);

        for (int kc = 0; kc < HH; kc += 128) {
            // stage h chunk: hs[b][0..127] <- h_in[b][kc..kc+127] (L1-bypass)
#pragma unroll
            for (int i = 0; i < 8; i++) {
                int f = tid + i * 256;          // 0..2047 float4 slots
                int b = f >> 5;
                int kq = f & 31;
                float4 v = __ldcg((const float4*)(h_in + (size_t)b * HH + kc) + kq);
                *((float4*)(hs + b * HS_STR) + kq) = v;
            }
            __syncthreads();

#pragma unroll 8
            for (int k4 = 0; k4 < 32; k4++) {
                float4 h4 = *(const float4*)(hs + bg * HS_STR + k4 * 4);
                float hv[4] = {h4.x, h4.y, h4.z, h4.w};
#pragma unroll
                for (int kk = 0; kk < 4; kk++) {
                    int k = kc + k4 * 4 + kk;
                    const uint64_t* ub = Us + (size_t)k * 16 + ju * 4;
                    ulonglong2 u01 = *(const ulonglong2*)ub;
                    ulonglong2 u23 = *(const ulonglong2*)(ub + 2);
                    uint64_t hp = pack_dup(hv[kk]);
                    fma2(acc[0], u01.x, hp);
                    fma2(acc[1], u01.y, hp);
                    fma2(acc[2], u23.x, hp);
                    fma2(acc[3], u23.y, hp);
                }
            }
            __syncthreads();
        }

        // elementwise: i,f,g,o
        float iE, iO, fE, fO, gE, gO, oE, oO, cE, cO;
        unpack2(acc[0], iE, iO);
        unpack2(acc[1], fE, fO);
        unpack2(acc[2], gE, gO);
        unpack2(acc[3], oE, oO);
        unpack2(cpair, cE, cO);

        float cnE = d_sigmoid(fE) * cE + d_sigmoid(iE) * d_tanh(gE);
        float cnO = d_sigmoid(fO) * cO + d_sigmoid(iO) * d_tanh(gO);
        float hnE = d_sigmoid(oE) * d_tanh(cnE);
        float hnO = d_sigmoid(oO) * d_tanh(cnO);
        cpair = pack2f(cnE, cnO);

        int hi = bg * HH + u0;
        *(float2*)&h_out[hi] = make_float2(hnE, hnO);
        *(float2*)&seq_out[(size_t)t * t_str + (size_t)bg * b_str + u0] = make_float2(hnE, hnO);
        if (t == TT - 1 && hT) {
            *(float2*)&hT[hi] = make_float2(hnE, hnO);
            *(float2*)&cT[hi] = make_float2(cnE, cnO);
        }
    }
}

// ---------------- launch ----------------
extern "C" void kernel_launch(void* const* d_in, const int* in_sizes, int n_in,
                              void* d_out, int out_size)
{
    const float* X  = (const float*)d_in[0];
    const float* h0 = (const float*)d_in[1];
    const float* c0 = (const float*)d_in[2];
    const float* W0 = (const float*)d_in[3];
    const float* U0 = (const float*)d_in[4];
    const float* b0 = (const float*)d_in[5];
    const float* W1 = (const float*)d_in[6];
    const float* U1 = (const float*)d_in[7];
    const float* b1 = (const float*)d_in[8];
    float* out = (float*)d_out;

    float *G, *hseq, *hping;
    float2 *Up0, *Up1;
    cudaGetSymbolAddress((void**)&G,     g_G);
    cudaGetSymbolAddress((void**)&hseq,  g_hseq);
    cudaGetSymbolAddress((void**)&Up0,   g_Up0);
    cudaGetSymbolAddress((void**)&Up1,   g_Up1);
    cudaGetSymbolAddress((void**)&hping, g_hping);

    cudaFuncSetAttribute(gemm_tf32, cudaFuncAttributeMaxDynamicSharedMemorySize, GSMEM);
    cudaFuncSetAttribute(lstm_layer, cudaFuncAttributeMaxDynamicSharedMemorySize, SMEM_LSTM);

    packU<<<(NBLK * HH * 16) / 256, 256>>>(U0, Up0);
    packU<<<(NBLK * HH * 16) / 256, 256>>>(U1, Up1);

    dim3 ggrid(G4 / 64, (TT * BB) / 128);   // (64, 256)

    bool wantHC = (size_t)out_size >= (size_t)BB * TT * HH + 2ull * BB * HH;
    float* hT = wantHC ? out + (size_t)BB * TT * HH : nullptr;
    float* cT = wantHC ? hT + (size_t)BB * HH : nullptr;

    // ---- layer 0 ----
    gemm_tf32<<<ggrid, 256, GSMEM>>>(X, W0, b0, G, DD, 0);
    lstm_layer<<<NBLK, 256, SMEM_LSTM>>>(G, Up0, h0, c0, hping,
                                         hseq, BB * HH, HH,
                                         nullptr, nullptr);

    // ---- layer 1 ----
    gemm_tf32<<<ggrid, 256, GSMEM>>>(hseq, W1, b1, G, HH, 1);
    lstm_layer<<<NBLK, 256, SMEM_LSTM>>>(G, Up1,
                                         h0 + (size_t)BB * HH, c0 + (size_t)BB * HH,
                                         hping,
                                         out, HH, TT * HH,
                                         hT, cT);
}

// round 7
// speedup vs baseline: 4.8698x; 2.4005x over previous
#include <cuda_runtime.h>
#include <cuda_bf16.h>
#include <math.h>
#include <stdint.h>

#define BB 64      // batch
#define TT 512     // seq len
#define DD 512     // input size
#define HH 1024    // hidden
#define G4 4096    // 4*HH
#define NBLK 128   // persistent blocks (1/SM, co-resident)

// ---------------- scratch (static __device__, no allocs) ----------------
__device__ float g_G[(size_t)TT * BB * G4];        // precomputed x@W+b, rows = (t,B)
__device__ float g_hseq[(size_t)TT * BB * HH];     // layer-0 hidden sequence (T,B,H)
__device__ uint32_t g_Ubhi0[(size_t)NBLK * 32 * 512];  // U0 hi bf16x2: [blk][n32][kp512]
__device__ uint32_t g_Ublo0[(size_t)NBLK * 32 * 512];
__device__ uint32_t g_Ubhi1[(size_t)NBLK * 32 * 512];
__device__ uint32_t g_Ublo1[(size_t)NBLK * 32 * 512];
__device__ uint32_t g_hbf[2 * 2 * BB * 512];       // [plane][ping][b][kp] bf16x2 h

// ---------------- software grid barrier (graph-replay safe: monotonic gen) --
__device__ unsigned g_cnt = 0;
__device__ volatile unsigned g_gen = 0;

__device__ __forceinline__ void grid_barrier() {
    __syncthreads();
    if (threadIdx.x == 0) {
        __threadfence();
        unsigned old = g_gen;
        if (atomicAdd(&g_cnt, 1) == NBLK - 1) {
            g_cnt = 0;
            __threadfence();
            g_gen = old + 1;
        } else {
            while (g_gen == old) { }
        }
        __threadfence();
    }
    __syncthreads();
}

__device__ __forceinline__ float d_sigmoid(float x) { return 1.0f / (1.0f + expf(-x)); }
__device__ __forceinline__ float d_tanh(float x)    { return 1.0f - 2.0f / (expf(2.0f * x) + 1.0f); }

// ---------------- tf32 helpers (big GEMMs, validated R4/R5) ----------------
__device__ __forceinline__ uint32_t f2tf(float x) {
    uint32_t r; asm("cvt.rna.tf32.f32 %0, %1;" : "=r"(r) : "f"(x)); return r;
}
__device__ __forceinline__ void cvt_pair(float x, uint32_t& hi, uint32_t& lo) {
    hi = f2tf(x);
    lo = f2tf(x - __uint_as_float(hi));
}
__device__ __forceinline__ void mma8(float* c, const uint32_t* a, const uint32_t* b) {
    asm volatile("mma.sync.aligned.m16n8k8.row.col.f32.tf32.tf32.f32 "
        "{%0,%1,%2,%3}, {%4,%5,%6,%7}, {%8,%9}, {%0,%1,%2,%3};\n"
        : "+f"(c[0]), "+f"(c[1]), "+f"(c[2]), "+f"(c[3])
        : "r"(a[0]), "r"(a[1]), "r"(a[2]), "r"(a[3]), "r"(b[0]), "r"(b[1]));
}

// ---------------- bf16 mma helper ----------------
__device__ __forceinline__ void mma16bf(float* c, const uint32_t* a, const uint32_t* b) {
    asm volatile("mma.sync.aligned.m16n8k16.row.col.f32.bf16.bf16.f32 "
        "{%0,%1,%2,%3}, {%4,%5,%6,%7}, {%8,%9}, {%0,%1,%2,%3};\n"
        : "+f"(c[0]), "+f"(c[1]), "+f"(c[2]), "+f"(c[3])
        : "r"(a[0]), "r"(a[1]), "r"(a[2]), "r"(a[3]), "r"(b[0]), "r"(b[1]));
}

__device__ __forceinline__ uint32_t pack_bf2(float a, float b) {
    __nv_bfloat162 v = __floats2bfloat162_rn(a, b);   // (a -> .x, b -> .y)
    return *(uint32_t*)&v;
}
__device__ __forceinline__ void split_bf(float x, float& hi_f, uint16_t& hi, uint16_t& lo) {
    __nv_bfloat16 h = __float2bfloat16_rn(x);
    hi_f = __bfloat162float(h);
    __nv_bfloat16 l = __float2bfloat16_rn(x - hi_f);
    hi = *(uint16_t*)&h; lo = *(uint16_t*)&l;
}

// ---------------- U pack: per block slice, bf16 hi/lo, [n][k-pair] ----------
// n = g*8 + u (gate-major within block), kp packs (2kp, 2kp+1)
__global__ void packUbf16(const float* __restrict__ U,
                          uint32_t* __restrict__ Uhi, uint32_t* __restrict__ Ulo) {
    int e = blockIdx.x * blockDim.x + threadIdx.x;    // over NBLK*32*512
    if (e >= NBLK * 32 * 512) return;
    int kp  = e & 511;
    int n   = (e >> 9) & 31;
    int blk = e >> 14;
    int g = n >> 3, u = n & 7;
    int col = g * HH + blk * 8 + u;
    float a = U[(size_t)(2 * kp) * G4 + col];
    float b = U[(size_t)(2 * kp + 1) * G4 + col];
    __nv_bfloat16 ah = __float2bfloat16_rn(a);
    __nv_bfloat16 bh = __float2bfloat16_rn(b);
    float ahf = __bfloat162float(ah), bhf = __bfloat162float(bh);
    __nv_bfloat16 al = __float2bfloat16_rn(a - ahf);
    __nv_bfloat16 bl = __float2bfloat16_rn(b - bhf);
    Uhi[e] = (uint32_t)*(uint16_t*)&ah | ((uint32_t)*(uint16_t*)&bh << 16);
    Ulo[e] = (uint32_t)*(uint16_t*)&al | ((uint32_t)*(uint16_t*)&bl << 16);
}

// ---------------- tensor-core 3xTF32 GEMM (validated) ----------------
#define KT 16
#define AS_STR 132
#define BS_STR 20
#define ASZ (KT * AS_STR)
#define BSZ (64 * BS_STR)
#define BUFSZ (2 * ASZ + 2 * BSZ)
#define GSMEM (2 * BUFSZ * 4)

__global__ __launch_bounds__(256, 2) void gemm_tf32(
    const float* __restrict__ A, const float* __restrict__ W,
    const float* __restrict__ bias, float* __restrict__ C, int K, int mode)
{
    extern __shared__ uint32_t sm[];
    int tid = threadIdx.x;
    int lane = tid & 31, wid = tid >> 5;
    int wm = wid & 3, wn = wid >> 2;
    int m0 = blockIdx.y * 128, n0 = blockIdx.x * 64;

    int amA = tid >> 2;
    int akA = (tid & 3) * 4;
    int mA0 = m0 + amA, mA1 = mA0 + 64;
    size_t r0 = (mode == 0) ? (size_t)(mA0 & 63) * TT + (mA0 >> 6) : (size_t)mA0;
    size_t r1 = (mode == 0) ? (size_t)(mA1 & 63) * TT + (mA1 >> 6) : (size_t)mA1;
    const float* pA0 = A + r0 * K + akA;
    const float* pA1 = A + r1 * K + akA;
    int bkB = tid >> 4;
    int bnB = (tid & 15) * 4;
    const float* pB = W + (size_t)bkB * G4 + n0 + bnB;

    float4 fa0 = *(const float4*)pA0; pA0 += KT;
    float4 fa1 = *(const float4*)pA1; pA1 += KT;
    float4 fb  = *(const float4*)pB;  pB  += (size_t)KT * G4;

    float acc[2][4][4];
#pragma unroll
    for (int mt = 0; mt < 2; mt++)
#pragma unroll
        for (int nt = 0; nt < 4; nt++)
#pragma unroll
            for (int i = 0; i < 4; i++) acc[mt][nt][i] = 0.0f;

    int nIter = K / KT;
    for (int it = 0; it < nIter; it++) {
        uint32_t* base = sm + (it & 1) * BUFSZ;
        uint32_t* ah = base;
        uint32_t* al = base + ASZ;
        uint32_t* bh = base + 2 * ASZ;
        uint32_t* bl = bh + BSZ;
        {
            float va[4]  = {fa0.x, fa0.y, fa0.z, fa0.w};
            float va2[4] = {fa1.x, fa1.y, fa1.z, fa1.w};
            float vw[4]  = {fb.x, fb.y, fb.z, fb.w};
#pragma unroll
            for (int j = 0; j < 4; j++) {
                uint32_t h, l;
                cvt_pair(va[j], h, l);
                ah[(akA + j) * AS_STR + amA] = h;
                al[(akA + j) * AS_STR + amA] = l;
                cvt_pair(va2[j], h, l);
                ah[(akA + j) * AS_STR + amA + 64] = h;
                al[(akA + j) * AS_STR + amA + 64] = l;
                cvt_pair(vw[j], h, l);
                bh[(bnB + j) * BS_STR + bkB] = h;
                bl[(bnB + j) * BS_STR + bkB] = l;
            }
        }
        __syncthreads();
        if (it + 1 < nIter) {
            fa0 = *(const float4*)pA0; pA0 += KT;
            fa1 = *(const float4*)pA1; pA1 += KT;
            fb  = *(const float4*)pB;  pB  += (size_t)KT * G4;
        }
#pragma unroll
        for (int ks = 0; ks < 2; ks++) {
            int kb = ks * 8 + (lane & 3);
            int ar = wm * 32 + (lane >> 2);
            uint32_t Ah[2][4], Al[2][4];
#pragma unroll
            for (int mt = 0; mt < 2; mt++) {
                int r = ar + mt * 16;
                Ah[mt][0] = ah[kb * AS_STR + r];
                Ah[mt][1] = ah[kb * AS_STR + r + 8];
                Ah[mt][2] = ah[(kb + 4) * AS_STR + r];
                Ah[mt][3] = ah[(kb + 4) * AS_STR + r + 8];
                Al[mt][0] = al[kb * AS_STR + r];
                Al[mt][1] = al[kb * AS_STR + r + 8];
                Al[mt][2] = al[(kb + 4) * AS_STR + r];
                Al[mt][3] = al[(kb + 4) * AS_STR + r + 8];
            }
            int bn = wn * 32 + (lane >> 2);
            int bk = ks * 8 + (lane & 3);
            uint32_t Bh[4][2], Bl[4][2];
#pragma unroll
            for (int nt = 0; nt < 4; nt++) {
                Bh[nt][0] = bh[(bn + nt * 8) * BS_STR + bk];
                Bh[nt][1] = bh[(bn + nt * 8) * BS_STR + bk + 4];
                Bl[nt][0] = bl[(bn + nt * 8) * BS_STR + bk];
                Bl[nt][1] = bl[(bn + nt * 8) * BS_STR + bk + 4];
            }
#pragma unroll
            for (int mt = 0; mt < 2; mt++)
#pragma unroll
                for (int nt = 0; nt < 4; nt++) {
                    mma8(acc[mt][nt], Ah[mt], Bh[nt]);
                    mma8(acc[mt][nt], Al[mt], Bh[nt]);
                    mma8(acc[mt][nt], Ah[mt], Bl[nt]);
                }
        }
    }
#pragma unroll
    for (int mt = 0; mt < 2; mt++)
#pragma unroll
        for (int nt = 0; nt < 4; nt++) {
            int gr = m0 + wm * 32 + mt * 16 + (lane >> 2);
            int gc = n0 + wn * 32 + nt * 8 + (lane & 3) * 2;
            float bz0 = bias[gc], bz1 = bias[gc + 1];
            float2 v0 = make_float2(acc[mt][nt][0] + bz0, acc[mt][nt][1] + bz1);
            float2 v1 = make_float2(acc[mt][nt][2] + bz0, acc[mt][nt][3] + bz1);
            *(float2*)&C[(size_t)gr * G4 + gc] = v0;
            *(float2*)&C[(size_t)(gr + 8) * G4 + gc] = v1;
        }
}

// ---------------- persistent recurrent layer: bf16x3 tensor-core ----------
// 128 blocks x 256 threads (8 warps). Block owns 8 units = 32 gate-cols
// (n = g*8 + u). Warp (wm=wid&3, wn=wid>>2): C tile rows 16wm..+15,
// cols 16wn..+15 of the 64x32 block tile. K=1024 in 8 chunks of 128.
// smem (u32 offsets):
#define SM_UHI 0                         // [32][516]
#define SM_ULO 16512                     // [32][516]
#define SM_HHI 33024                     // [64][68]
#define SM_HLO 37376                     // [64][68]
#define SM_CS  41728                     // [64][34] f32
#define SM_TOT (43904 * 4)               // 175616 bytes
#define USTR 516
#define HSTR 68
#define CSTR 34

__global__ __launch_bounds__(256, 1) void lstm_mma(
    const float* __restrict__ Gbase,     // (T, B, 4H)
    const uint32_t* __restrict__ Ubhi,   // [blk][32][512]
    const uint32_t* __restrict__ Ublo,
    const float* __restrict__ h0,
    const float* __restrict__ c0,
    uint32_t* __restrict__ hpp,          // g_hbf: [plane][ping][64][512]
    float* __restrict__ seq_out, int t_str, int b_str,
    float* hT, float* cT)
{
    extern __shared__ uint32_t sm[];
    float* smf = (float*)sm;
    int tid = threadIdx.x;
    int lane = tid & 31, wid = tid >> 5;
    int wm = wid & 3, wn = wid >> 2;
    int t4 = lane & 3, g8 = lane >> 2;
    int blk = blockIdx.x;

    // ---- load U slice to smem (once) ----
    {
        const float4* shi = (const float4*)(Ubhi + (size_t)blk * 32 * 512);
        const float4* slo = (const float4*)(Ublo + (size_t)blk * 32 * 512);
#pragma unroll
        for (int i = 0; i < 16; i++) {
            int f = tid + i * 256;           // 4096 float4 per plane
            int n = f >> 7, c = f & 127;     // 128 float4 per 512-u32 row
            *(float4*)&sm[SM_UHI + n * USTR + c * 4] = shi[f];
            *(float4*)&sm[SM_ULO + n * USTR + c * 4] = slo[f];
        }
    }

    // ---- init h planes (ping 0) from h0; c in registers ----
    for (int slot = blk * 256 + tid; slot < BB * 512; slot += NBLK * 256) {
        int b = slot >> 9, kp = slot & 511;
        float x = h0[b * HH + 2 * kp], y = h0[b * HH + 2 * kp + 1];
        float xh, yh; uint16_t xhi, xlo, yhi, ylo;
        split_bf(x, xh, xhi, xlo);
        split_bf(y, yh, yhi, ylo);
        hpp[0 * 65536 + 0 * 32768 + slot] = (uint32_t)xhi | ((uint32_t)yhi << 16);
        hpp[1 * 65536 + 0 * 32768 + slot] = (uint32_t)xlo | ((uint32_t)ylo << 16);
    }
    int ju = tid & 3, bg = tid >> 2;
    int u0g = blk * 8 + 2 * ju;              // global unit (even)
    int kp_own = blk * 4 + ju;               // u32 slot of own unit pair
    float cE = c0[bg * HH + u0g], cO = c0[bg * HH + u0g + 1];

    for (int t = 0; t < TT; t++) {
        grid_barrier();   // prior h writes visible

        const uint32_t* hin_hi = hpp + 0 * 65536 + (t & 1) * 32768;
        const uint32_t* hin_lo = hpp + 1 * 65536 + (t & 1) * 32768;
        uint32_t* hout_hi = hpp + 0 * 65536 + ((t + 1) & 1) * 32768;
        uint32_t* hout_lo = hpp + 1 * 65536 + ((t + 1) & 1) * 32768;
        const float* Gt = Gbase + (size_t)t * BB * G4;

        // ---- init accumulators from G ----
        float acc[2][4];
        {
            int r0 = 16 * wm + g8;
#pragma unroll
            for (int nt = 0; nt < 2; nt++) {
                int gcol = (2 * wn + nt) * HH + blk * 8 + 2 * t4;
                float2 v0 = *(const float2*)&Gt[(size_t)r0 * G4 + gcol];
                float2 v1 = *(const float2*)&Gt[(size_t)(r0 + 8) * G4 + gcol];
                acc[nt][0] = v0.x; acc[nt][1] = v0.y;
                acc[nt][2] = v1.x; acc[nt][3] = v1.y;
            }
        }

        // ---- stage assignment: thread covers 4 float4 per plane per chunk ----
        int srow[4], scol[4];
#pragma unroll
        for (int j = 0; j < 4; j++) {
            int f = tid + j * 256;           // 0..1023
            srow[j] = f >> 4;                // 64 rows
            scol[j] = f & 15;                // 16 float4 per row-chunk
        }
        float4 rhi[4], rlo[4];
#pragma unroll
        for (int j = 0; j < 4; j++) {
            rhi[j] = ((const float4*)(hin_hi + srow[j] * 512))[scol[j]];
            rlo[j] = ((const float4*)(hin_lo + srow[j] * 512))[scol[j]];
        }

        for (int kc = 0; kc < 8; kc++) {
            // store staged regs
#pragma unroll
            for (int j = 0; j < 4; j++) {
                *(float4*)&sm[SM_HHI + srow[j] * HSTR + scol[j] * 4] = rhi[j];
                *(float4*)&sm[SM_HLO + srow[j] * HSTR + scol[j] * 4] = rlo[j];
            }
            __syncthreads();
            // prefetch next chunk
            if (kc < 7) {
#pragma unroll
                for (int j = 0; j < 4; j++) {
                    rhi[j] = ((const float4*)(hin_hi + srow[j] * 512 + (kc + 1) * 64))[scol[j]];
                    rlo[j] = ((const float4*)(hin_lo + srow[j] * 512 + (kc + 1) * 64))[scol[j]];
                }
            }
            // 8 x k16 mma
#pragma unroll
            for (int kk = 0; kk < 8; kk++) {
                int ko = kk * 8 + t4;
                int ar0 = 16 * wm + g8;
                uint32_t Ah[4], Al[4];
                Ah[0] = sm[SM_HHI + ar0 * HSTR + ko];
                Ah[1] = sm[SM_HHI + (ar0 + 8) * HSTR + ko];
                Ah[2] = sm[SM_HHI + ar0 * HSTR + ko + 4];
                Ah[3] = sm[SM_HHI + (ar0 + 8) * HSTR + ko + 4];
                Al[0] = sm[SM_HLO + ar0 * HSTR + ko];
                Al[1] = sm[SM_HLO + (ar0 + 8) * HSTR + ko];
                Al[2] = sm[SM_HLO + ar0 * HSTR + ko + 4];
                Al[3] = sm[SM_HLO + (ar0 + 8) * HSTR + ko + 4];
                int ku = kc * 64 + kk * 8 + t4;
#pragma unroll
                for (int nt = 0; nt < 2; nt++) {
                    int n = 16 * wn + nt * 8 + g8;
                    uint32_t Bh[2], Bl[2];
                    Bh[0] = sm[SM_UHI + n * USTR + ku];
                    Bh[1] = sm[SM_UHI + n * USTR + ku + 4];
                    Bl[0] = sm[SM_ULO + n * USTR + ku];
                    Bl[1] = sm[SM_ULO + n * USTR + ku + 4];
                    mma16bf(acc[nt], Ah, Bh);
                    mma16bf(acc[nt], Al, Bh);
                    mma16bf(acc[nt], Ah, Bl);
                }
            }
            __syncthreads();
        }

        // ---- C frags -> smem ----
        {
            int r0 = 16 * wm + g8;
#pragma unroll
            for (int nt = 0; nt < 2; nt++) {
                int nc = 16 * wn + nt * 8 + 2 * t4;
                smf[SM_CS + r0 * CSTR + nc]       = acc[nt][0];
                smf[SM_CS + r0 * CSTR + nc + 1]   = acc[nt][1];
                smf[SM_CS + (r0 + 8) * CSTR + nc]     = acc[nt][2];
                smf[SM_CS + (r0 + 8) * CSTR + nc + 1] = acc[nt][3];
            }
        }
        __syncthreads();

        // ---- elementwise (thread = (bg, ju)) ----
        {
            const float* crow = smf + SM_CS + bg * CSTR;
            float2 gi = *(const float2*)&crow[0 * 8 + 2 * ju];
            float2 gf = *(const float2*)&crow[1 * 8 + 2 * ju];
            float2 gg = *(const float2*)&crow[2 * 8 + 2 * ju];
            float2 go = *(const float2*)&crow[3 * 8 + 2 * ju];

            float cnE = d_sigmoid(gf.x) * cE + d_sigmoid(gi.x) * d_tanh(gg.x);
            float cnO = d_sigmoid(gf.y) * cO + d_sigmoid(gi.y) * d_tanh(gg.y);
            float hnE = d_sigmoid(go.x) * d_tanh(cnE);
            float hnO = d_sigmoid(go.y) * d_tanh(cnO);
            cE = cnE; cO = cnO;

            // write fp32 sequence output
            *(float2*)&seq_out[(size_t)t * t_str + (size_t)bg * b_str + u0g] =
                make_float2(hnE, hnO);
            // write bf16 hi/lo planes for next step
            float hEf, hOf; uint16_t Ehi, Elo, Ohi, Olo;
            split_bf(hnE, hEf, Ehi, Elo);
            split_bf(hnO, hOf, Ohi, Olo);
            int slot = bg * 512 + kp_own;
            hout_hi[slot] = (uint32_t)Ehi | ((uint32_t)Ohi << 16);
            hout_lo[slot] = (uint32_t)Elo | ((uint32_t)Olo << 16);

            if (t == TT - 1 && hT) {
                int hi = bg * HH + u0g;
                *(float2*)&hT[hi] = make_float2(hnE, hnO);
                *(float2*)&cT[hi] = make_float2(cnE, cnO);
            }
        }
        // next grid_barrier() starts with __syncthreads -> Cs reuse safe
    }
}

// ---------------- launch ----------------
extern "C" void kernel_launch(void* const* d_in, const int* in_sizes, int n_in,
                              void* d_out, int out_size)
{
    const float* X  = (const float*)d_in[0];
    const float* h0 = (const float*)d_in[1];
    const float* c0 = (const float*)d_in[2];
    const float* W0 = (const float*)d_in[3];
    const float* U0 = (const float*)d_in[4];
    const float* b0 = (const float*)d_in[5];
    const float* W1 = (const float*)d_in[6];
    const float* U1 = (const float*)d_in[7];
    const float* b1 = (const float*)d_in[8];
    float* out = (float*)d_out;

    float *G, *hseq;
    uint32_t *Uh0, *Ul0, *Uh1, *Ul1, *hbf;
    cudaGetSymbolAddress((void**)&G,    g_G);
    cudaGetSymbolAddress((void**)&hseq, g_hseq);
    cudaGetSymbolAddress((void**)&Uh0,  g_Ubhi0);
    cudaGetSymbolAddress((void**)&Ul0,  g_Ublo0);
    cudaGetSymbolAddress((void**)&Uh1,  g_Ubhi1);
    cudaGetSymbolAddress((void**)&Ul1,  g_Ublo1);
    cudaGetSymbolAddress((void**)&hbf,  g_hbf);

    cudaFuncSetAttribute(gemm_tf32, cudaFuncAttributeMaxDynamicSharedMemorySize, GSMEM);
    cudaFuncSetAttribute(lstm_mma,  cudaFuncAttributeMaxDynamicSharedMemorySize, SM_TOT);

    packUbf16<<<(NBLK * 32 * 512) / 256, 256>>>(U0, Uh0, Ul0);
    packUbf16<<<(NBLK * 32 * 512) / 256, 256>>>(U1, Uh1, Ul1);

    dim3 ggrid(G4 / 64, (TT * BB) / 128);   // (64, 256)

    bool wantHC = (size_t)out_size >= (size_t)BB * TT * HH + 2ull * BB * HH;
    float* hT = wantHC ? out + (size_t)BB * TT * HH : nullptr;
    float* cT = wantHC ? hT + (size_t)BB * HH : nullptr;

    // ---- layer 0 ----
    gemm_tf32<<<ggrid, 256, GSMEM>>>(X, W0, b0, G, DD, 0);
    lstm_mma<<<NBLK, 256, SM_TOT>>>(G, Uh0, Ul0, h0, c0, hbf,
                                    hseq, BB * HH, HH,
                                    nullptr, nullptr);

    // ---- layer 1 ----
    gemm_tf32<<<ggrid, 256, GSMEM>>>(hseq, W1, b1, G, HH, 1);
    lstm_mma<<<NBLK, 256, SM_TOT>>>(G, Uh1, Ul1,
                                    h0 + (size_t)BB * HH, c0 + (size_t)BB * HH,
                                    hbf,
                                    out, HH, TT * HH,
                                    hT, cT);
}

// round 8
// speedup vs baseline: 5.9106x; 1.2137x over previous
#include <cuda_runtime.h>
#include <cuda_bf16.h>
#include <math.h>
#include <stdint.h>

#define BB 64      // batch
#define TT 512     // seq len
#define DD 512     // input size
#define HH 1024    // hidden
#define G4 4096    // 4*HH
#define NBLK 128   // persistent blocks (1/SM, co-resident)

// ---------------- scratch (static __device__, no allocs) ----------------
__device__ float g_G[(size_t)TT * BB * G4];
__device__ float g_hseq[(size_t)TT * BB * HH];
__device__ uint32_t g_Ubhi0[(size_t)NBLK * 32 * 512];  // [blk][n32][kp512] bf16x2 hi
__device__ uint32_t g_Ublo0[(size_t)NBLK * 32 * 512];
__device__ uint32_t g_Ubhi1[(size_t)NBLK * 32 * 512];
__device__ uint32_t g_Ublo1[(size_t)NBLK * 32 * 512];
__device__ uint32_t g_hbf[2 * 2 * BB * 512];       // [plane][ping][b][kp]

// ---------------- software grid barrier ----------------
__device__ unsigned g_cnt = 0;
__device__ volatile unsigned g_gen = 0;

__device__ __forceinline__ void grid_barrier() {
    __syncthreads();
    if (threadIdx.x == 0) {
        __threadfence();
        unsigned old = g_gen;
        if (atomicAdd(&g_cnt, 1) == NBLK - 1) {
            g_cnt = 0;
            __threadfence();
            g_gen = old + 1;
        } else {
            while (g_gen == old) { }
        }
        __threadfence();
    }
    __syncthreads();
}

__device__ __forceinline__ float d_sigmoid(float x) { return 1.0f / (1.0f + expf(-x)); }
__device__ __forceinline__ float d_tanh(float x)    { return 1.0f - 2.0f / (expf(2.0f * x) + 1.0f); }

// ---------------- bf16 helpers ----------------
__device__ __forceinline__ void mma16bf(float* c, const uint32_t* a, const uint32_t* b) {
    asm volatile("mma.sync.aligned.m16n8k16.row.col.f32.bf16.bf16.f32 "
        "{%0,%1,%2,%3}, {%4,%5,%6,%7}, {%8,%9}, {%0,%1,%2,%3};\n"
        : "+f"(c[0]), "+f"(c[1]), "+f"(c[2]), "+f"(c[3])
        : "r"(a[0]), "r"(a[1]), "r"(a[2]), "r"(a[3]), "r"(b[0]), "r"(b[1]));
}
__device__ __forceinline__ void split_bf(float x, float& hi_f, uint16_t& hi, uint16_t& lo) {
    __nv_bfloat16 h = __float2bfloat16_rn(x);
    hi_f = __bfloat162float(h);
    __nv_bfloat16 l = __float2bfloat16_rn(x - hi_f);
    hi = *(uint16_t*)&h; lo = *(uint16_t*)&l;
}
// pack two fp32 -> bf16x2 (a in low half), plus residual pack
__device__ __forceinline__ void pack_hl(float a, float b, uint32_t& hi, uint32_t& lo) {
    __nv_bfloat16 ah = __float2bfloat16_rn(a);
    __nv_bfloat16 bh = __float2bfloat16_rn(b);
    __nv_bfloat16 al = __float2bfloat16_rn(a - __bfloat162float(ah));
    __nv_bfloat16 bl = __float2bfloat16_rn(b - __bfloat162float(bh));
    hi = (uint32_t)*(uint16_t*)&ah | ((uint32_t)*(uint16_t*)&bh << 16);
    lo = (uint32_t)*(uint16_t*)&al | ((uint32_t)*(uint16_t*)&bl << 16);
}

// ---------------- U pack (validated R6) ----------------
__global__ void packUbf16(const float* __restrict__ U,
                          uint32_t* __restrict__ Uhi, uint32_t* __restrict__ Ulo) {
    int e = blockIdx.x * blockDim.x + threadIdx.x;    // over NBLK*32*512
    if (e >= NBLK * 32 * 512) return;
    int kp  = e & 511;
    int n   = (e >> 9) & 31;
    int blk = e >> 14;
    int g = n >> 3, u = n & 7;
    int col = g * HH + blk * 8 + u;
    uint32_t hi, lo;
    pack_hl(U[(size_t)(2 * kp) * G4 + col], U[(size_t)(2 * kp + 1) * G4 + col], hi, lo);
    Uhi[e] = hi; Ulo[e] = lo;
}

// ---------------- bf16x3 big GEMM ----------------
// C[m][n] = A[rowmap(m)][:] @ W[:, n] + bias[n]; block 128x64, KT=32, 8 warps.
#define KTG 32
#define A_STR 20                 // u32 stride per m row (16 kp + 4 pad)
#define B_STR 20                 // u32 stride per n row
#define A_PL (128 * A_STR)       // 2560
#define B_PL (64 * B_STR)        // 1280
#define GBUF (2 * A_PL + 2 * B_PL)   // 7680 u32 per buffer
#define GSMEM (2 * GBUF * 4)         // 61440 bytes

__global__ __launch_bounds__(256, 2) void gemm_bf16(
    const float* __restrict__ A, const float* __restrict__ W,
    const float* __restrict__ bias, float* __restrict__ C, int K, int mode)
{
    extern __shared__ uint32_t sm[];
    int tid = threadIdx.x;
    int lane = tid & 31, wid = tid >> 5;
    int wm = wid & 3, wn = wid >> 2;
    int t4 = lane & 3, g8 = lane >> 2;
    int m0 = blockIdx.y * 128, n0 = blockIdx.x * 64;

    // A staging: thread covers 4 (m, k-quad) float4 slots
    const float* pA[4];
    int amL[4], akq[4];
#pragma unroll
    for (int j = 0; j < 4; j++) {
        int idx = tid + j * 256;      // 0..1023
        int m = idx >> 3;             // 0..127
        int kq = idx & 7;             // k = 4kq..4kq+3
        amL[j] = m; akq[j] = kq;
        int gm = m0 + m;
        size_t row = (mode == 0) ? (size_t)(gm & 63) * TT + (gm >> 6) : (size_t)gm;
        pA[j] = A + row * K + 4 * kq;
    }
    // B staging: thread covers n = tid&63, k rows 8kg..8kg+7
    int nB = tid & 63, kg = tid >> 6;
    const float* pB = W + (size_t)(8 * kg) * G4 + n0 + nB;

    float4 fa[4];
    float fbr[8];
#pragma unroll
    for (int j = 0; j < 4; j++) fa[j] = *(const float4*)pA[j];
#pragma unroll
    for (int s = 0; s < 8; s++) fbr[s] = pB[(size_t)s * G4];

    float acc[2][4][4];
#pragma unroll
    for (int mt = 0; mt < 2; mt++)
#pragma unroll
        for (int nt = 0; nt < 4; nt++)
#pragma unroll
            for (int i = 0; i < 4; i++) acc[mt][nt][i] = 0.0f;

    int nIter = K / KTG;
    for (int it = 0; it < nIter; it++) {
        uint32_t* base = sm + (it & 1) * GBUF;
        uint32_t* ahi = base;
        uint32_t* alo = base + A_PL;
        uint32_t* bhi = base + 2 * A_PL;
        uint32_t* blo = bhi + B_PL;

        // stage A
#pragma unroll
        for (int j = 0; j < 4; j++) {
            uint32_t h0, l0, h1, l1;
            pack_hl(fa[j].x, fa[j].y, h0, l0);
            pack_hl(fa[j].z, fa[j].w, h1, l1);
            int off = amL[j] * A_STR + 2 * akq[j];
            ahi[off] = h0; ahi[off + 1] = h1;
            alo[off] = l0; alo[off + 1] = l1;
        }
        // stage B: pack k pairs, 4 consecutive kp -> STS.128
        {
            uint32_t h[4], l[4];
#pragma unroll
            for (int p = 0; p < 4; p++)
                pack_hl(fbr[2 * p], fbr[2 * p + 1], h[p], l[p]);
            int off = nB * B_STR + 4 * kg;
            *(uint4*)&bhi[off] = make_uint4(h[0], h[1], h[2], h[3]);
            *(uint4*)&blo[off] = make_uint4(l[0], l[1], l[2], l[3]);
        }
        __syncthreads();

        // prefetch next chunk
        if (it + 1 < nIter) {
#pragma unroll
            for (int j = 0; j < 4; j++) { pA[j] += KTG; fa[j] = *(const float4*)pA[j]; }
            pB += (size_t)KTG * G4;
#pragma unroll
            for (int s = 0; s < 8; s++) fbr[s] = pB[(size_t)s * G4];
        }

        // compute: 2 x k16
#pragma unroll
        for (int ks = 0; ks < 2; ks++) {
            int ko = ks * 8 + t4;
            uint32_t Ah[2][4], Al[2][4];
#pragma unroll
            for (int mt = 0; mt < 2; mt++) {
                int r = (wm * 32 + mt * 16 + g8) * A_STR;
                Ah[mt][0] = ahi[r + ko];
                Ah[mt][1] = ahi[r + 8 * A_STR + ko];
                Ah[mt][2] = ahi[r + ko + 4];
                Ah[mt][3] = ahi[r + 8 * A_STR + ko + 4];
                Al[mt][0] = alo[r + ko];
                Al[mt][1] = alo[r + 8 * A_STR + ko];
                Al[mt][2] = alo[r + ko + 4];
                Al[mt][3] = alo[r + 8 * A_STR + ko + 4];
            }
#pragma unroll
            for (int nt = 0; nt < 4; nt++) {
                int nr = (wn * 32 + nt * 8 + g8) * B_STR;
                uint32_t Bh[2] = { bhi[nr + ko], bhi[nr + ko + 4] };
                uint32_t Bl[2] = { blo[nr + ko], blo[nr + ko + 4] };
#pragma unroll
                for (int mt = 0; mt < 2; mt++) {
                    mma16bf(acc[mt][nt], Ah[mt], Bh);
                    mma16bf(acc[mt][nt], Al[mt], Bh);
                    mma16bf(acc[mt][nt], Ah[mt], Bl);
                }
            }
        }
        // (double-buffer: reuse distance 2 iterations, next sync protects)
    }

#pragma unroll
    for (int mt = 0; mt < 2; mt++)
#pragma unroll
        for (int nt = 0; nt < 4; nt++) {
            int gr = m0 + wm * 32 + mt * 16 + g8;
            int gc = n0 + wn * 32 + nt * 8 + 2 * t4;
            float bz0 = bias[gc], bz1 = bias[gc + 1];
            float2 v0 = make_float2(acc[mt][nt][0] + bz0, acc[mt][nt][1] + bz1);
            float2 v1 = make_float2(acc[mt][nt][2] + bz0, acc[mt][nt][3] + bz1);
            *(float2*)&C[(size_t)gr * G4 + gc] = v0;
            *(float2*)&C[(size_t)(gr + 8) * G4 + gc] = v1;
        }
}

// ---------------- persistent recurrent layer v2: 512 thr, 16 warps ---------
// Warp (wm=wid&3 -> rows 16wm..+15, wn=wid>>2 -> cols 8wn..+7 = gate wn).
// K=1024 in 4 chunks of 256 values (128 kp).
#define SM_UHI 0                          // [32][516]
#define SM_ULO 16512
#define SM_HHI 33024                      // [64][132]
#define SM_HLO 41472
#define SM_CS  49920                      // [64][34] f32
#define SM_TOT ((49920 + 64 * 34) * 4)    // 208384 bytes
#define USTR 516
#define HSTR 132
#define CSTR 34

__global__ __launch_bounds__(512, 1) void lstm_mma(
    const float* __restrict__ Gbase,
    const uint32_t* __restrict__ Ubhi,
    const uint32_t* __restrict__ Ublo,
    const float* __restrict__ h0,
    const float* __restrict__ c0,
    uint32_t* __restrict__ hpp,
    float* __restrict__ seq_out, int t_str, int b_str,
    float* hT, float* cT)
{
    extern __shared__ uint32_t sm[];
    float* smf = (float*)sm;
    int tid = threadIdx.x;
    int lane = tid & 31, wid = tid >> 5;
    int wm = wid & 3, wn = wid >> 2;
    int t4 = lane & 3, g8 = lane >> 2;
    int blk = blockIdx.x;

    // ---- load U slice (once) ----
    {
        const float4* shi = (const float4*)(Ubhi + (size_t)blk * 32 * 512);
        const float4* slo = (const float4*)(Ublo + (size_t)blk * 32 * 512);
#pragma unroll
        for (int i = 0; i < 8; i++) {
            int f = tid + i * 512;           // 4096 float4 per plane
            int n = f >> 7, c = f & 127;
            *(float4*)&sm[SM_UHI + n * USTR + c * 4] = shi[f];
            *(float4*)&sm[SM_ULO + n * USTR + c * 4] = slo[f];
        }
    }

    // ---- init h planes (ping 0); c in regs for tid<256 ----
    for (int slot = blk * 512 + tid; slot < BB * 512; slot += NBLK * 512) {
        int b = slot >> 9, kp = slot & 511;
        uint32_t hi, lo;
        pack_hl(h0[b * HH + 2 * kp], h0[b * HH + 2 * kp + 1], hi, lo);
        hpp[0 * 65536 + 0 * 32768 + slot] = hi;
        hpp[1 * 65536 + 0 * 32768 + slot] = lo;
    }
    int ju = tid & 3, bg = tid >> 2;
    int u0g = blk * 8 + 2 * ju;
    int kp_own = blk * 4 + ju;
    float cE = 0.f, cO = 0.f;
    if (tid < 256) { cE = c0[bg * HH + u0g]; cO = c0[bg * HH + u0g + 1]; }

    // staging map: 4 float4 per plane per chunk
    int srow[4], scol[4];
#pragma unroll
    for (int j = 0; j < 4; j++) {
        int f = tid + j * 512;               // 0..2047
        srow[j] = f >> 5; scol[j] = f & 31;
    }
    int r0 = 16 * wm + g8;
    int gcol = wn * HH + blk * 8 + 2 * t4;

    for (int t = 0; t < TT; t++) {
        // ---- prefetch G accumulators BEFORE barrier (G independent of h) ----
        const float* Gt = Gbase + (size_t)t * BB * G4;
        float2 v0 = *(const float2*)&Gt[(size_t)r0 * G4 + gcol];
        float2 v1 = *(const float2*)&Gt[(size_t)(r0 + 8) * G4 + gcol];
        float acc[4] = { v0.x, v0.y, v1.x, v1.y };

        grid_barrier();   // prior h writes visible

        const uint32_t* hin_hi = hpp + 0 * 65536 + (t & 1) * 32768;
        const uint32_t* hin_lo = hpp + 1 * 65536 + (t & 1) * 32768;
        uint32_t* hout_hi = hpp + 0 * 65536 + ((t + 1) & 1) * 32768;
        uint32_t* hout_lo = hpp + 1 * 65536 + ((t + 1) & 1) * 32768;

        float4 rhi[4], rlo[4];
#pragma unroll
        for (int j = 0; j < 4; j++) {
            rhi[j] = ((const float4*)(hin_hi + srow[j] * 512))[scol[j]];
            rlo[j] = ((const float4*)(hin_lo + srow[j] * 512))[scol[j]];
        }

        for (int kc = 0; kc < 4; kc++) {
#pragma unroll
            for (int j = 0; j < 4; j++) {
                *(float4*)&sm[SM_HHI + srow[j] * HSTR + scol[j] * 4] = rhi[j];
                *(float4*)&sm[SM_HLO + srow[j] * HSTR + scol[j] * 4] = rlo[j];
            }
            __syncthreads();
            if (kc < 3) {
#pragma unroll
                for (int j = 0; j < 4; j++) {
                    rhi[j] = ((const float4*)(hin_hi + srow[j] * 512 + (kc + 1) * 128))[scol[j]];
                    rlo[j] = ((const float4*)(hin_lo + srow[j] * 512 + (kc + 1) * 128))[scol[j]];
                }
            }
#pragma unroll
            for (int kk = 0; kk < 16; kk++) {
                int ko = kk * 8 + t4;
                uint32_t Ah[4], Al[4];
                Ah[0] = sm[SM_HHI + r0 * HSTR + ko];
                Ah[1] = sm[SM_HHI + (r0 + 8) * HSTR + ko];
                Ah[2] = sm[SM_HHI + r0 * HSTR + ko + 4];
                Ah[3] = sm[SM_HHI + (r0 + 8) * HSTR + ko + 4];
                Al[0] = sm[SM_HLO + r0 * HSTR + ko];
                Al[1] = sm[SM_HLO + (r0 + 8) * HSTR + ko];
                Al[2] = sm[SM_HLO + r0 * HSTR + ko + 4];
                Al[3] = sm[SM_HLO + (r0 + 8) * HSTR + ko + 4];
                int n = 8 * wn + g8;
                int ku = kc * 128 + kk * 8 + t4;
                uint32_t Bh[2] = { sm[SM_UHI + n * USTR + ku], sm[SM_UHI + n * USTR + ku + 4] };
                uint32_t Bl[2] = { sm[SM_ULO + n * USTR + ku], sm[SM_ULO + n * USTR + ku + 4] };
                mma16bf(acc, Ah, Bh);
                mma16bf(acc, Al, Bh);
                mma16bf(acc, Ah, Bl);
            }
            __syncthreads();
        }

        // ---- C frags -> smem ----
        {
            int nc = 8 * wn + 2 * t4;
            smf[SM_CS + r0 * CSTR + nc]           = acc[0];
            smf[SM_CS + r0 * CSTR + nc + 1]       = acc[1];
            smf[SM_CS + (r0 + 8) * CSTR + nc]     = acc[2];
            smf[SM_CS + (r0 + 8) * CSTR + nc + 1] = acc[3];
        }
        __syncthreads();

        // ---- elementwise (tid < 256: thread = (bg, ju)) ----
        if (tid < 256) {
            const float* crow = smf + SM_CS + bg * CSTR;
            float2 gi = *(const float2*)&crow[0 * 8 + 2 * ju];
            float2 gf = *(const float2*)&crow[1 * 8 + 2 * ju];
            float2 gg = *(const float2*)&crow[2 * 8 + 2 * ju];
            float2 go = *(const float2*)&crow[3 * 8 + 2 * ju];

            float cnE = d_sigmoid(gf.x) * cE + d_sigmoid(gi.x) * d_tanh(gg.x);
            float cnO = d_sigmoid(gf.y) * cO + d_sigmoid(gi.y) * d_tanh(gg.y);
            float hnE = d_sigmoid(go.x) * d_tanh(cnE);
            float hnO = d_sigmoid(go.y) * d_tanh(cnO);
            cE = cnE; cO = cnO;

            *(float2*)&seq_out[(size_t)t * t_str + (size_t)bg * b_str + u0g] =
                make_float2(hnE, hnO);
            uint32_t hi, lo;
            pack_hl(hnE, hnO, hi, lo);
            int slot = bg * 512 + kp_own;
            hout_hi[slot] = hi;
            hout_lo[slot] = lo;

            if (t == TT - 1 && hT) {
                int hidx = bg * HH + u0g;
                *(float2*)&hT[hidx] = make_float2(hnE, hnO);
                *(float2*)&cT[hidx] = make_float2(cnE, cnO);
            }
        }
    }
}

// ---------------- launch ----------------
extern "C" void kernel_launch(void* const* d_in, const int* in_sizes, int n_in,
                              void* d_out, int out_size)
{
    const float* X  = (const float*)d_in[0];
    const float* h0 = (const float*)d_in[1];
    const float* c0 = (const float*)d_in[2];
    const float* W0 = (const float*)d_in[3];
    const float* U0 = (const float*)d_in[4];
    const float* b0 = (const float*)d_in[5];
    const float* W1 = (const float*)d_in[6];
    const float* U1 = (const float*)d_in[7];
    const float* b1 = (const float*)d_in[8];
    float* out = (float*)d_out;

    float *G, *hseq;
    uint32_t *Uh0, *Ul0, *Uh1, *Ul1, *hbf;
    cudaGetSymbolAddress((void**)&G,    g_G);
    cudaGetSymbolAddress((void**)&hseq, g_hseq);
    cudaGetSymbolAddress((void**)&Uh0,  g_Ubhi0);
    cudaGetSymbolAddress((void**)&Ul0,  g_Ublo0);
    cudaGetSymbolAddress((void**)&Uh1,  g_Ubhi1);
    cudaGetSymbolAddress((void**)&Ul1,  g_Ublo1);
    cudaGetSymbolAddress((void**)&hbf,  g_hbf);

    cudaFuncSetAttribute(gemm_bf16, cudaFuncAttributeMaxDynamicSharedMemorySize, GSMEM);
    cudaFuncSetAttribute(lstm_mma,  cudaFuncAttributeMaxDynamicSharedMemorySize, SM_TOT);

    packUbf16<<<(NBLK * 32 * 512) / 256, 256>>>(U0, Uh0, Ul0);
    packUbf16<<<(NBLK * 32 * 512) / 256, 256>>>(U1, Uh1, Ul1);

    dim3 ggrid(G4 / 64, (TT * BB) / 128);   // (64, 256)

    bool wantHC = (size_t)out_size >= (size_t)BB * TT * HH + 2ull * BB * HH;
    float* hT = wantHC ? out + (size_t)BB * TT * HH : nullptr;
    float* cT = wantHC ? hT + (size_t)BB * HH : nullptr;

    // ---- layer 0 ----
    gemm_bf16<<<ggrid, 256, GSMEM>>>(X, W0, b0, G, DD, 0);
    lstm_mma<<<NBLK, 512, SM_TOT>>>(G, Uh0, Ul0, h0, c0, hbf,
                                    hseq, BB * HH, HH,
                                    nullptr, nullptr);

    // ---- layer 1 ----
    gemm_bf16<<<ggrid, 256, GSMEM>>>(hseq, W1, b1, G, HH, 1);
    lstm_mma<<<NBLK, 512, SM_TOT>>>(G, Uh1, Ul1,
                                    h0 + (size_t)BB * HH, c0 + (size_t)BB * HH,
                                    hbf,
                                    out, HH, TT * HH,
                                    hT, cT);
}